// round 13
// baseline (speedup 1.0000x reference)
#include <cuda_runtime.h>
#include <cuda_bf16.h>
#include <cstdint>

#define NN 50000
#define NE 400000
#define DD 128
#define MM 4
#define NPAD (NN + 128)

// ---------------- device scratch ----------------
__device__ __align__(16) float g_H[NN * DD];    // H = gelu(X W1^T + b1), fp32
__device__ __align__(16) float g_T[NN * MM];    // per-node hyper weights
// pre-split pair buffers (bf16x2 hi/lo), fragment-physical layout, 64 pairs/row
__device__ __align__(16) unsigned g_Hhi[64 * NPAD];
__device__ __align__(16) unsigned g_Hlo[64 * NPAD];
__device__ __align__(16) unsigned g_Hghi[64 * NPAD]; // gelu(H) split
__device__ __align__(16) unsigned g_Hglo[64 * NPAD];
__device__ __align__(16) unsigned g_Agghi[64 * NPAD]; // gelu(agg) split
__device__ __align__(16) unsigned g_Agglo[64 * NPAD];
// pre-split weights
__device__ __align__(16) unsigned g_W1hi[DD * DD / 2];
__device__ __align__(16) unsigned g_W1lo[DD * DD / 2];
__device__ __align__(16) unsigned g_WAhi[DD * DD / 2];
__device__ __align__(16) unsigned g_WAlo[DD * DD / 2];
__device__ __align__(16) unsigned g_W2hi[DD * DD];
__device__ __align__(16) unsigned g_W2lo[DD * DD];
__device__ int g_deg[NN];
__device__ int g_off[NN + 1];
__device__ int g_cur[NN];
__device__ int g_srcs[NE];
__device__ int g_is32; // 1 if edge_index is int32, 0 if int64

__device__ __forceinline__ const unsigned* get_whi(int id) {
    switch (id) {
        case 0: return g_W1hi;
        case 1: return g_WAhi;
        case 2: return g_W2hi;
    }
    return g_W1hi;
}
__device__ __forceinline__ const unsigned* get_wlo(int id) {
    switch (id) {
        case 0: return g_W1lo;
        case 1: return g_WAlo;
        case 2: return g_W2lo;
    }
    return g_W1lo;
}
// pre-split A sources: 0 = H, 1 = gelu(agg), 2 = gelu(H)
__device__ __forceinline__ const unsigned* get_ahi(int id) {
    switch (id) {
        case 0: return g_Hhi;
        case 1: return g_Agghi;
        case 2: return g_Hghi;
    }
    return g_Hhi;
}
__device__ __forceinline__ const unsigned* get_alo(int id) {
    switch (id) {
        case 0: return g_Hlo;
        case 1: return g_Agglo;
        case 2: return g_Hglo;
    }
    return g_Hlo;
}

// ---------------- helpers ----------------
__device__ __forceinline__ float gelu_f(float x) {
    return 0.5f * x * (1.0f + erff(x * 0.7071067811865476f));
}

__device__ __forceinline__ unsigned pack2bf(float x, float y) {
    __nv_bfloat162 p = __floats2bfloat162_rn(x, y);
    return *reinterpret_cast<unsigned*>(&p);
}

// split (x,y) into hi bf16 pair + residual-lo bf16 pair
__device__ __forceinline__ void split2(float x, float y, unsigned& hi, unsigned& lo) {
    __nv_bfloat16 hx = __float2bfloat16(x);
    __nv_bfloat16 hy = __float2bfloat16(y);
    __nv_bfloat162 ph;
    ph.x = hx;
    ph.y = hy;
    hi = *reinterpret_cast<unsigned*>(&ph);
    lo = pack2bf(x - __bfloat162float(hx), y - __bfloat162float(hy));
}

__device__ __forceinline__ void mma_bf16(float* d, const unsigned* a,
                                         unsigned b0, unsigned b1) {
    asm volatile(
        "mma.sync.aligned.m16n8k16.row.col.f32.bf16.bf16.f32 "
        "{%0,%1,%2,%3}, {%4,%5,%6,%7}, {%8,%9}, {%0,%1,%2,%3};\n"
        : "+f"(d[0]), "+f"(d[1]), "+f"(d[2]), "+f"(d[3])
        : "r"(a[0]), "r"(a[1]), "r"(a[2]), "r"(a[3]), "r"(b0), "r"(b1));
}

// physical column for logical k-pair p within an 8-pair (k16) group
__device__ __forceinline__ int physcol8(int p) {
    return ((p & 3) << 1) | (p >> 2);
}

__device__ __forceinline__ uint32_t smem_u32(const void* p) {
    uint32_t a;
    asm("{ .reg .u64 t; cvta.to.shared.u64 t, %1; cvt.u32.u64 %0, t; }"
        : "=r"(a) : "l"(p));
    return a;
}

#define CP_ASYNC16(dst, src) \
    asm volatile("cp.async.cg.shared.global [%0], [%1], 16;" \
                 :: "r"(dst), "l"(src) : "memory")
#define CP_COMMIT() asm volatile("cp.async.commit_group;" ::: "memory")
#define CP_WAIT0() asm volatile("cp.async.wait_group 0;" ::: "memory")

// edge accessor robust to int32 vs int64 storage. which: 0 = src, 1 = dst.
__device__ __forceinline__ int edge_at(const void* EI, int which, int e) {
    if (g_is32) return ((const int*)EI)[which * NE + e];
    return (int)((const long long*)EI)[which * NE + e];
}

// ---------------- init ----------------
__global__ void k_zerodeg() {
    int i = blockIdx.x * blockDim.x + threadIdx.x;
    if (i < NN) g_deg[i] = 0;
    if (i == 0) g_is32 = 0;
}

__global__ void k_detect(const unsigned int* __restrict__ w) {
    unsigned v = 0;
    for (int j = blockIdx.x * blockDim.x + threadIdx.x; j < NE;
         j += gridDim.x * blockDim.x)
        v |= w[2 * j + 1];
    if (v) g_is32 = 1;
}

// ---------------- pre-split weights (pre-permuted per 8-pair group) -------
__global__ void k_wsplit(const float* __restrict__ W1, const float* __restrict__ WA,
                         const float* __restrict__ W2) {
    int i = blockIdx.x * blockDim.x + threadIdx.x;
    if (i >= 32768) return;
    const float* src;
    unsigned *dh, *dl;
    int p, K2len;
    if (i < 8192) {
        src = W1; dh = g_W1hi; dl = g_W1lo; p = i; K2len = 64;
    } else if (i < 16384) {
        src = WA; dh = g_WAhi; dl = g_WAlo; p = i - 8192; K2len = 64;
    } else {
        src = W2; dh = g_W2hi; dl = g_W2lo; p = i - 16384; K2len = 128;
    }
    float2 v = *(const float2*)(src + 2 * p);
    unsigned h, l;
    split2(v.x, v.y, h, l);
    int n = p / K2len, col = p % K2len;
    int pc = (col & ~7) | physcol8(col & 7);
    dh[n * K2len + pc] = h;
    dl[n * K2len + pc] = l;
}

// ---------------- bf16-split tensor-core GEMM, double-buffered ------------
// C[m][n] = act( sum_k A[m][k] * W[n][k] + bias[n] ),  N = 128.
// PRE: A pre-split in global (aId; DUAL switches to a2Id for k>=128) ->
//      staging is pure cp.async. Otherwise A = fp32 ext, split in-kernel.
// TMIX: T[m][j] = sum_n gelu(C[m][n]) * WB[j][n], no C write.
// WSPLIT: C fp32 write + H/gelu(H) pre-split pair writes (GEMM1).
template <int K, bool GOUT, bool BIAS, bool PRE, bool DUAL, bool TMIX, bool WSPLIT>
__global__ void __launch_bounds__(256, 2)
k_gemm_bf(const float* __restrict__ Aext, int aId, int a2Id,
          const float* __restrict__ bias, int wId, const float* __restrict__ WB,
          float* __restrict__ Cext, int cId, int rows) {
    // row stride 12 (48 B) keeps every cp.async 16B destination 16-aligned
    __shared__ __align__(16) unsigned sA[2][2][128][12]; // [stage][hi/lo][m][pc]
    __shared__ __align__(16) unsigned sB[2][2][128][12]; // [stage][hi/lo][n][pc]

    const unsigned* Whi = get_whi(wId);
    const unsigned* Wlo = get_wlo(wId);
    const unsigned* pAhi = PRE ? get_ahi(aId) : nullptr;
    const unsigned* pAlo = PRE ? get_alo(aId) : nullptr;
    const unsigned* pA2hi = (PRE && DUAL) ? get_ahi(a2Id) : nullptr;
    const unsigned* pA2lo = (PRE && DUAL) ? get_alo(a2Id) : nullptr;
    float* C = Cext ? Cext : g_H;
    const int K2 = K / 2;
    const int NCH = K / 16;

    int tid = threadIdx.x;
    int wid = tid >> 5, lane = tid & 31;
    int wm = (wid >> 1) * 32;  // warp M base
    int wn = (wid & 1) * 64;   // warp N base
    int g = lane >> 2, tg = lane & 3;
    int m0 = blockIdx.x * 128;

    float d[2][8][4];
#pragma unroll
    for (int t = 0; t < 2; t++)
#pragma unroll
        for (int nt = 0; nt < 8; nt++)
#pragma unroll
            for (int j = 0; j < 4; j++) d[t][nt][j] = 0.f;

    int brow = tid >> 1, bq = tid & 1;
    auto stageB = [&](int s, int c) {
        uint32_t d0 = smem_u32(&sB[s][0][brow][bq * 4]);
        CP_ASYNC16(d0, Whi + (long)brow * K2 + 8 * c + 4 * bq);
        uint32_t d1 = smem_u32(&sB[s][1][brow][bq * 4]);
        CP_ASYNC16(d1, Wlo + (long)brow * K2 + 8 * c + 4 * bq);
    };
    auto stageA_cp = [&](int s, int c) {
        const unsigned* Ah = pAhi;
        const unsigned* Al = pAlo;
        int grp = c;
        if (DUAL && c >= 8) {
            Ah = pA2hi;
            Al = pA2lo;
            grp = c - 8;
        }
        long off = (long)(m0 + brow) * 64 + 8 * grp + 4 * bq;
        CP_ASYNC16(smem_u32(&sA[s][0][brow][bq * 4]), Ah + off);
        CP_ASYNC16(smem_u32(&sA[s][1][brow][bq * 4]), Al + off);
    };
    auto ldgA = [&](int c, float4* vr) {
        int kk = c * 16;
#pragma unroll
        for (int i = 0; i < 2; ++i) {
            int f = tid + (i << 8);
            int m = f >> 2, kq = (f & 3) << 2;
            int gm = m0 + m;
            vr[i] = (gm < rows) ? *(const float4*)(Aext + (long)gm * 128 + kk + kq)
                                : make_float4(0.f, 0.f, 0.f, 0.f);
        }
    };
    auto stsA = [&](int s, float4* vr) {
#pragma unroll
        for (int i = 0; i < 2; ++i) {
            int f = tid + (i << 8);
            int m = f >> 2, kq = (f & 3) << 2;
            int p = kq >> 1; // even
            int c0 = physcol8(p);
            float4 v = vr[i];
            unsigned h0, l0, h1, l1;
            split2(v.x, v.y, h0, l0);
            split2(v.z, v.w, h1, l1);
            sA[s][0][m][c0] = h0; sA[s][0][m][c0 + 2] = h1;
            sA[s][1][m][c0] = l0; sA[s][1][m][c0 + 2] = l1;
        }
    };
    auto domma = [&](int s) {
        unsigned ah[2][4], al[2][4];
#pragma unroll
        for (int t = 0; t < 2; t++) {
            int r0 = wm + t * 16 + g;
            uint2 u0 = *(const uint2*)&sA[s][0][r0][2 * tg];
            uint2 u1 = *(const uint2*)&sA[s][0][r0 + 8][2 * tg];
            ah[t][0] = u0.x; ah[t][1] = u1.x; ah[t][2] = u0.y; ah[t][3] = u1.y;
            uint2 w0 = *(const uint2*)&sA[s][1][r0][2 * tg];
            uint2 w1 = *(const uint2*)&sA[s][1][r0 + 8][2 * tg];
            al[t][0] = w0.x; al[t][1] = w1.x; al[t][2] = w0.y; al[t][3] = w1.y;
        }
#pragma unroll
        for (int nt = 0; nt < 8; nt++) {
            int n0 = wn + nt * 8 + g;
            uint2 bh = *(const uint2*)&sB[s][0][n0][2 * tg];
            uint2 bl = *(const uint2*)&sB[s][1][n0][2 * tg];
#pragma unroll
            for (int t = 0; t < 2; t++) {
                mma_bf16(d[t][nt], ah[t], bh.x, bh.y); // hi*hi
                mma_bf16(d[t][nt], al[t], bh.x, bh.y); // lo*hi
                mma_bf16(d[t][nt], ah[t], bl.x, bl.y); // hi*lo
            }
        }
    };

    // ---- prologue ----
    if (PRE) {
        stageA_cp(0, 0);
        stageB(0, 0);
        CP_COMMIT();
        CP_WAIT0();
    } else {
        stageB(0, 0);
        CP_COMMIT();
        float4 v0[2];
        ldgA(0, v0);
        stsA(0, v0);
        CP_WAIT0();
    }
    __syncthreads();

    // ---- pipelined mainloop ----
    float4 vr[2];
    for (int c = 0; c < NCH; ++c) {
        int cs = c & 1, ns = cs ^ 1;
        bool more = (c + 1 < NCH);
        if (more) {
            if (PRE) {
                stageA_cp(ns, c + 1);
                stageB(ns, c + 1);
                CP_COMMIT();
            } else {
                stageB(ns, c + 1);
                CP_COMMIT();
                ldgA(c + 1, vr);
            }
        }
        domma(cs);
        if (more) {
            if (!PRE) stsA(ns, vr);
            CP_WAIT0();
        }
        __syncthreads();
    }

    // ---------------- epilogue ----------------
    if (TMIX) {
        float* wbs = (float*)sA;               // 512 floats, aliased
        float* Tred = (float*)&sA[0][1][0][0]; // 512 floats, aliased
        for (int i = tid; i < 512; i += 256) wbs[i] = WB[i];
        if (tid < 128) {
            Tred[tid * 4 + 0] = 0.f; Tred[tid * 4 + 1] = 0.f;
            Tred[tid * 4 + 2] = 0.f; Tred[tid * 4 + 3] = 0.f;
        }
        __syncthreads();
        float tp[4][4];
#pragma unroll
        for (int s = 0; s < 4; s++)
#pragma unroll
            for (int m = 0; m < 4; m++) tp[s][m] = 0.f;
#pragma unroll
        for (int t = 0; t < 2; t++) {
#pragma unroll
            for (int nt = 0; nt < 8; nt++) {
                int c = wn + nt * 8 + 2 * tg;
                float v0 = gelu_f(d[t][nt][0]), v1 = gelu_f(d[t][nt][1]);
                float v2 = gelu_f(d[t][nt][2]), v3 = gelu_f(d[t][nt][3]);
#pragma unroll
                for (int m = 0; m < 4; m++) {
                    float w0 = wbs[m * 128 + c], w1 = wbs[m * 128 + c + 1];
                    tp[t * 2 + 0][m] += v0 * w0 + v1 * w1;
                    tp[t * 2 + 1][m] += v2 * w0 + v3 * w1;
                }
            }
        }
#pragma unroll
        for (int off = 1; off < 4; off <<= 1)
#pragma unroll
            for (int s = 0; s < 4; s++)
#pragma unroll
                for (int m = 0; m < 4; m++)
                    tp[s][m] += __shfl_xor_sync(0xffffffffu, tp[s][m], off);
        if (tg == 0) {
#pragma unroll
            for (int s = 0; s < 4; s++) {
                int rl = wm + g + ((s & 1) ? 8 : 0) + ((s >> 1) ? 16 : 0);
#pragma unroll
                for (int m = 0; m < 4; m++) atomicAdd(&Tred[rl * 4 + m], tp[s][m]);
            }
        }
        __syncthreads();
        if (tid < 128) {
            int r = m0 + tid;
            if (r < rows)
                *(float4*)(g_T + (long)r * 4) =
                    make_float4(Tred[tid * 4 + 0], Tred[tid * 4 + 1],
                                Tred[tid * 4 + 2], Tred[tid * 4 + 3]);
        }
    } else if (WSPLIT) {
        // GEMM1: write H fp32 + pre-split H pairs + pre-split gelu(H) pairs
#pragma unroll
        for (int t = 0; t < 2; t++) {
            int r = m0 + wm + t * 16 + g;
#pragma unroll
            for (int q = 0; q < 4; q++) {
                float va[2][4];
#pragma unroll
                for (int w = 0; w < 2; w++) {
                    int nt = 2 * q + w;
                    int c = wn + nt * 8 + 2 * tg;
                    float b0 = bias[c], b1 = bias[c + 1];
                    va[w][0] = gelu_f(d[t][nt][0] + b0);
                    va[w][1] = gelu_f(d[t][nt][1] + b1);
                    va[w][2] = gelu_f(d[t][nt][2] + b0);
                    va[w][3] = gelu_f(d[t][nt][3] + b1);
                }
                int cb = wn + 16 * q + 2 * tg;
                long pb = (long)(wn >> 1) + 8 * q + 2 * tg;
                if (r < rows) {
                    *(float2*)(C + (long)r * 128 + cb) = make_float2(va[0][0], va[0][1]);
                    *(float2*)(C + (long)r * 128 + cb + 8) = make_float2(va[1][0], va[1][1]);
                    unsigned ha, la, hb, lb;
                    split2(va[0][0], va[0][1], ha, la);
                    split2(va[1][0], va[1][1], hb, lb);
                    long ix = (long)r * 64 + pb;
                    *(uint2*)(g_Hhi + ix) = make_uint2(ha, hb);
                    *(uint2*)(g_Hlo + ix) = make_uint2(la, lb);
                    float g0 = gelu_f(va[0][0]), g1 = gelu_f(va[0][1]);
                    float g2 = gelu_f(va[1][0]), g3 = gelu_f(va[1][1]);
                    split2(g0, g1, ha, la);
                    split2(g2, g3, hb, lb);
                    *(uint2*)(g_Hghi + ix) = make_uint2(ha, hb);
                    *(uint2*)(g_Hglo + ix) = make_uint2(la, lb);
                }
                if (r + 8 < rows) {
                    *(float2*)(C + (long)(r + 8) * 128 + cb) = make_float2(va[0][2], va[0][3]);
                    *(float2*)(C + (long)(r + 8) * 128 + cb + 8) = make_float2(va[1][2], va[1][3]);
                    unsigned ha, la, hb, lb;
                    split2(va[0][2], va[0][3], ha, la);
                    split2(va[1][2], va[1][3], hb, lb);
                    long ix = (long)(r + 8) * 64 + pb;
                    *(uint2*)(g_Hhi + ix) = make_uint2(ha, hb);
                    *(uint2*)(g_Hlo + ix) = make_uint2(la, lb);
                    float g0 = gelu_f(va[0][2]), g1 = gelu_f(va[0][3]);
                    float g2 = gelu_f(va[1][2]), g3 = gelu_f(va[1][3]);
                    split2(g0, g1, ha, la);
                    split2(g2, g3, hb, lb);
                    *(uint2*)(g_Hghi + ix) = make_uint2(ha, hb);
                    *(uint2*)(g_Hglo + ix) = make_uint2(la, lb);
                }
            }
        }
    } else {
#pragma unroll
        for (int t = 0; t < 2; t++) {
            int r = m0 + wm + t * 16 + g;
#pragma unroll
            for (int nt = 0; nt < 8; nt++) {
                int c = wn + nt * 8 + 2 * tg;
                float b0 = 0.f, b1 = 0.f;
                if (BIAS) { b0 = bias[c]; b1 = bias[c + 1]; }
                float v0 = d[t][nt][0] + b0, v1 = d[t][nt][1] + b1;
                float v2 = d[t][nt][2] + b0, v3 = d[t][nt][3] + b1;
                if (GOUT) {
                    v0 = gelu_f(v0); v1 = gelu_f(v1);
                    v2 = gelu_f(v2); v3 = gelu_f(v3);
                }
                if (r < rows)
                    *(float2*)(C + (long)r * 128 + c) = make_float2(v0, v1);
                if (r + 8 < rows)
                    *(float2*)(C + (long)(r + 8) * 128 + c) = make_float2(v2, v3);
            }
        }
    }
}

// ---------------- edge counting sort by dst ----------------
__global__ void k_hist(const void* __restrict__ EI) {
    for (int e = blockIdx.x * blockDim.x + threadIdx.x; e < NE;
         e += gridDim.x * blockDim.x) {
        int d = edge_at(EI, 1, e);
        if (d >= 0 && d < NN) atomicAdd(&g_deg[d], 1);
    }
}

__global__ void k_scan() {
    __shared__ int smv[1024];
    int t = threadIdx.x;
    const int CH = 49; // 1024*49 >= 50000
    int base = t * CH;
    int s = 0;
    for (int i = 0; i < CH; i++) {
        int idx = base + i;
        if (idx < NN) s += g_deg[idx];
    }
    smv[t] = s;
    __syncthreads();
    for (int off = 1; off < 1024; off <<= 1) {
        int v = (t >= off) ? smv[t - off] : 0;
        __syncthreads();
        smv[t] += v;
        __syncthreads();
    }
    int run = smv[t] - s;
    for (int i = 0; i < CH; i++) {
        int idx = base + i;
        if (idx < NN) {
            g_off[idx] = run;
            g_cur[idx] = run;
            run += g_deg[idx];
        }
    }
    if (t == 0) g_off[NN] = NE;
}

__global__ void k_scatter(const void* __restrict__ EI) {
    for (int e = blockIdx.x * blockDim.x + threadIdx.x; e < NE;
         e += gridDim.x * blockDim.x) {
        int d = edge_at(EI, 1, e);
        int s = edge_at(EI, 0, e);
        if (d >= 0 && d < NN) {
            int p = atomicAdd(&g_cur[d], 1);
            g_srcs[p] = s;
        }
    }
}

// ---------------- per-node aggregation (warp per node, 4-edge unroll) -----
// lane handles 4 contiguous H columns (float4 gather); output written as
// pre-split bf16 pairs for GEMM3.
__global__ void k_agg() {
    int warp = threadIdx.x >> 5, lane = threadIdx.x & 31;
    int n = blockIdx.x * 8 + warp;
    if (n >= NN) return;
    int beg = g_off[n], end = g_off[n + 1];
    float acc[4][4]; // [col within float4][mix]
#pragma unroll
    for (int sg = 0; sg < 4; sg++)
#pragma unroll
        for (int m = 0; m < 4; m++) acc[sg][m] = 0.f;
    float S[4] = {0, 0, 0, 0};
    int i = beg;
    for (; i + 3 < end; i += 4) {
        int s[4];
        float4 t4[4];
        float4 h4[4];
#pragma unroll
        for (int e = 0; e < 4; e++) s[e] = g_srcs[i + e];
#pragma unroll
        for (int e = 0; e < 4; e++) {
            t4[e] = *(const float4*)(g_T + (long)s[e] * 4);
            h4[e] = *(const float4*)(g_H + (long)s[e] * 128 + 4 * lane);
        }
#pragma unroll
        for (int e = 0; e < 4; e++) {
            float tm[4] = {t4[e].x, t4[e].y, t4[e].z, t4[e].w};
            float hv[4] = {h4[e].x, h4[e].y, h4[e].z, h4[e].w};
#pragma unroll
            for (int m = 0; m < 4; m++) {
                S[m] += tm[m];
#pragma unroll
                for (int sg = 0; sg < 4; sg++) acc[sg][m] += hv[sg] * tm[m];
            }
        }
    }
    for (; i < end; ++i) {
        int s0 = g_srcs[i];
        float4 t4 = *(const float4*)(g_T + (long)s0 * 4);
        float4 h4 = *(const float4*)(g_H + (long)s0 * 128 + 4 * lane);
        float tm[4] = {t4.x, t4.y, t4.z, t4.w};
        float hv[4] = {h4.x, h4.y, h4.z, h4.w};
#pragma unroll
        for (int m = 0; m < 4; m++) {
            S[m] += tm[m];
#pragma unroll
            for (int sg = 0; sg < 4; sg++) acc[sg][m] += hv[sg] * tm[m];
        }
    }
    int cnt = end - beg;
    float inv = 1.0f / (float)(cnt > 1 ? cnt : 1);
    float o[4];
#pragma unroll
    for (int sg = 0; sg < 4; sg++) {
        o[sg] = gelu_f(
            (gelu_f(acc[sg][0]) * S[0] + gelu_f(acc[sg][1]) * S[1] +
             gelu_f(acc[sg][2]) * S[2] + gelu_f(acc[sg][3]) * S[3]) * inv);
    }
    // write pre-split pairs (fragment-physical layout)
    int p0 = 2 * lane, p1 = 2 * lane + 1;
    long i0 = (long)n * 64 + (p0 & ~7) + physcol8(p0 & 7);
    long i1 = (long)n * 64 + (p1 & ~7) + physcol8(p1 & 7);
    unsigned h0, l0, h1, l1;
    split2(o[0], o[1], h0, l0);
    split2(o[2], o[3], h1, l1);
    g_Agghi[i0] = h0; g_Agglo[i0] = l0;
    g_Agghi[i1] = h1; g_Agglo[i1] = l1;
}

// ---------------- host launch: kernel launches ONLY ----------------
extern "C" void kernel_launch(void* const* d_in, const int* in_sizes, int n_in,
                              void* d_out, int out_size) {
    const float* X = (const float*)d_in[0];
    const void* EI = d_in[1];
    const float* W1 = (const float*)d_in[2];
    const float* b1 = (const float*)d_in[3];
    const float* WA = (const float*)d_in[4];
    const float* WB = (const float*)d_in[5];
    const float* W2 = (const float*)d_in[6];
    const float* b2 = (const float*)d_in[7];
    float* out = (float*)d_out;

    k_zerodeg<<<(NN + 255) / 256, 256>>>();
    k_detect<<<256, 256>>>((const unsigned int*)EI);
    k_wsplit<<<128, 256>>>(W1, WA, W2);

    int gg = (NN + 127) / 128; // 391
    // GEMM1: H = gelu(X W1^T + b1); also emits pre-split H and gelu(H)
    k_gemm_bf<128, true, true, false, false, false, true><<<gg, 256>>>(
        X, -1, -1, b1, 0, nullptr, nullptr, -1, NN);
    // GEMM2: T = gelu(H WA^T) WB^T   (A = pre-split H, pure cp.async)
    k_gemm_bf<128, true, false, true, false, true, false><<<gg, 256>>>(
        nullptr, 0, -1, nullptr, 1, WB, nullptr, -1, NN);

    // edge counting sort by dst
    k_hist<<<512, 256>>>(EI);
    k_scan<<<1, 1024>>>();
    k_scatter<<<512, 256>>>(EI);

    // fused aggregation -> pre-split gelu(agg) pairs
    k_agg<<<(NN + 7) / 8, 256>>>();

    // GEMM3: out = [gelu(agg) | gelu(H)] W2^T + b2  (both halves pre-split)
    k_gemm_bf<256, false, true, true, true, false, false><<<gg, 256>>>(
        nullptr, 1, 2, b2, 2, nullptr, out, -1, NN);
}

// round 14
// speedup vs baseline: 1.1399x; 1.1399x over previous
#include <cuda_runtime.h>
#include <cuda_fp16.h>
#include <cstdint>

#define NN 50000
#define NE 400000
#define DD 128
#define MM 4

// ---------------- device scratch ----------------
__device__ __align__(16) float g_H[NN * DD];       // 1: H = gelu(X W1^T + b1)
__device__ __align__(16) float g_aggnode[NN * DD]; // 5: gelu(aggregated features)
__device__ __align__(16) float g_T[NN * MM];       // per-node hyper weights
// pre-packed fp16 weight pairs (hi only), fragment-physical pair order
__device__ __align__(16) unsigned g_W1h[DD * DD / 2];
__device__ __align__(16) unsigned g_WAh[DD * DD / 2];
__device__ __align__(16) unsigned g_W2h[DD * DD];
__device__ int g_deg[NN];
__device__ int g_off[NN + 1];
__device__ int g_cur[NN];
__device__ int g_srcs[NE];
__device__ int g_is32; // 1 if edge_index is int32, 0 if int64

__device__ __forceinline__ float* get_buf(int id) {
    switch (id) {
        case 1: return g_H;
        case 5: return g_aggnode;
    }
    return g_H;
}
__device__ __forceinline__ const unsigned* get_wh(int id) {
    switch (id) {
        case 0: return g_W1h;
        case 1: return g_WAh;
        case 2: return g_W2h;
    }
    return g_W1h;
}

// ---------------- helpers ----------------
__device__ __forceinline__ float gelu_f(float x) {
    return 0.5f * x * (1.0f + erff(x * 0.7071067811865476f));
}

__device__ __forceinline__ unsigned pack2h(float x, float y) {
    __half2 p = __floats2half2_rn(x, y);
    return *reinterpret_cast<unsigned*>(&p);
}

// split (x,y) into fp16 hi pair + fp16 residual-lo pair (A is exact to 2^-24)
__device__ __forceinline__ void split2h(float x, float y, unsigned& hi, unsigned& lo) {
    __half hx = __float2half_rn(x);
    __half hy = __float2half_rn(y);
    __half2 ph;
    ph.x = hx;
    ph.y = hy;
    hi = *reinterpret_cast<unsigned*>(&ph);
    lo = pack2h(x - __half2float(hx), y - __half2float(hy));
}

__device__ __forceinline__ void mma_f16(float* d, const unsigned* a,
                                        unsigned b0, unsigned b1) {
    asm volatile(
        "mma.sync.aligned.m16n8k16.row.col.f32.f16.f16.f32 "
        "{%0,%1,%2,%3}, {%4,%5,%6,%7}, {%8,%9}, {%0,%1,%2,%3};\n"
        : "+f"(d[0]), "+f"(d[1]), "+f"(d[2]), "+f"(d[3])
        : "r"(a[0]), "r"(a[1]), "r"(a[2]), "r"(a[3]), "r"(b0), "r"(b1));
}

// physical column for logical k-pair p within an 8-pair (k16) group
__device__ __forceinline__ int physcol8(int p) {
    return ((p & 3) << 1) | (p >> 2);
}

__device__ __forceinline__ uint32_t smem_u32(const void* p) {
    uint32_t a;
    asm("{ .reg .u64 t; cvta.to.shared.u64 t, %1; cvt.u32.u64 %0, t; }"
        : "=r"(a) : "l"(p));
    return a;
}

#define CP_ASYNC16(dst, src) \
    asm volatile("cp.async.cg.shared.global [%0], [%1], 16;" \
                 :: "r"(dst), "l"(src) : "memory")
#define CP_COMMIT() asm volatile("cp.async.commit_group;" ::: "memory")
#define CP_WAIT0() asm volatile("cp.async.wait_group 0;" ::: "memory")

// edge accessor robust to int32 vs int64 storage. which: 0 = src, 1 = dst.
__device__ __forceinline__ int edge_at(const void* EI, int which, int e) {
    if (g_is32) return ((const int*)EI)[which * NE + e];
    return (int)((const long long*)EI)[which * NE + e];
}

// ---------------- init ----------------
__global__ void k_zerodeg() {
    int i = blockIdx.x * blockDim.x + threadIdx.x;
    if (i < NN) g_deg[i] = 0;
    if (i == 0) g_is32 = 0;
}

__global__ void k_detect(const unsigned int* __restrict__ w) {
    unsigned v = 0;
    for (int j = blockIdx.x * blockDim.x + threadIdx.x; j < NE;
         j += gridDim.x * blockDim.x)
        v |= w[2 * j + 1];
    if (v) g_is32 = 1;
}

// ---------------- pre-pack weights to fp16 pairs (pre-permuted) -----------
__global__ void k_wsplit(const float* __restrict__ W1, const float* __restrict__ WA,
                         const float* __restrict__ W2) {
    int i = blockIdx.x * blockDim.x + threadIdx.x;
    if (i >= 32768) return;
    const float* src;
    unsigned* dh;
    int p, K2len;
    if (i < 8192) {
        src = W1; dh = g_W1h; p = i; K2len = 64;
    } else if (i < 16384) {
        src = WA; dh = g_WAh; p = i - 8192; K2len = 64;
    } else {
        src = W2; dh = g_W2h; p = i - 16384; K2len = 128;
    }
    float2 v = *(const float2*)(src + 2 * p);
    int n = p / K2len, col = p % K2len;
    int pc = (col & ~7) | physcol8(col & 7);
    dh[n * K2len + pc] = pack2h(v.x, v.y);
}

// ---------------- fp16 2-term tensor-core GEMM, double-buffered -----------
// C[m][n] = act( sum_k A[m][k] * W[n][k] + bias[n] ),  N = 128.
// A fp32 row-major stride 128 (SPLITA: k<128 from A1, k>=128 from gelu(A2));
// split in-kernel to fp16 hi+lo (A exact). B = pre-packed fp16 (hi only):
// D = Ah*B + Al*B. CTA 128x128, 8 warps (4Mx2N), warp 32x64, k-chunk 16.
// TMIX: skip C write; instead T[m][j] = sum_n gelu(C[m][n]) * WB[j][n].
template <int K, bool GOUT, bool BIAS, bool SPLITA, bool TMIX>
__global__ void __launch_bounds__(256, 2)
k_gemm_hf(const float* __restrict__ Aext, int aId, int a2Id,
          const float* __restrict__ bias, int wId, const float* __restrict__ WB,
          float* __restrict__ Cext, int cId, int rows) {
    __shared__ __align__(16) unsigned sA[2][2][128][12]; // [stage][hi/lo][m][pc]
    __shared__ __align__(16) unsigned sB[2][128][12];    // [stage][n][pc]

    const float* A1 = Aext ? Aext : get_buf(aId);
    const float* A2 = SPLITA ? get_buf(a2Id) : nullptr;
    const unsigned* Wh = get_wh(wId);
    float* C = Cext ? Cext : get_buf(cId);
    const int K2 = K / 2;
    const int NCH = K / 16;

    int tid = threadIdx.x;
    int wid = tid >> 5, lane = tid & 31;
    int wm = (wid >> 1) * 32;  // warp M base
    int wn = (wid & 1) * 64;   // warp N base
    int g = lane >> 2, tg = lane & 3;
    int m0 = blockIdx.x * 128;

    float d[2][8][4];
#pragma unroll
    for (int t = 0; t < 2; t++)
#pragma unroll
        for (int nt = 0; nt < 8; nt++)
#pragma unroll
            for (int j = 0; j < 4; j++) d[t][nt][j] = 0.f;

    int brow = tid >> 1, bq = tid & 1; // 256 threads: 128 rows x 2 quads
    auto stageB = [&](int s, int c) {
        uint32_t d0 = smem_u32(&sB[s][brow][bq * 4]);
        CP_ASYNC16(d0, Wh + (long)brow * K2 + 8 * c + 4 * bq);
    };
    auto ldgA = [&](int c, float4* vr) {
        const float* Ap = A1;
        int kk = c * 16;
        if (SPLITA && kk >= 128) { Ap = A2; kk -= 128; }
#pragma unroll
        for (int i = 0; i < 2; ++i) {
            int f = tid + (i << 8);
            int m = f >> 2, kq = (f & 3) << 2;
            int gm = m0 + m;
            vr[i] = (gm < rows) ? *(const float4*)(Ap + (long)gm * 128 + kk + kq)
                                : make_float4(0.f, 0.f, 0.f, 0.f);
        }
    };
    auto stsA = [&](int s, int c, float4* vr) {
        bool ag = SPLITA && (c * 16 >= 128);
#pragma unroll
        for (int i = 0; i < 2; ++i) {
            int f = tid + (i << 8);
            int m = f >> 2, kq = (f & 3) << 2;
            int p = kq >> 1; // even
            int c0 = physcol8(p);
            float4 v = vr[i];
            if (ag) {
                v.x = gelu_f(v.x); v.y = gelu_f(v.y);
                v.z = gelu_f(v.z); v.w = gelu_f(v.w);
            }
            unsigned h0, l0, h1, l1;
            split2h(v.x, v.y, h0, l0);
            split2h(v.z, v.w, h1, l1);
            sA[s][0][m][c0] = h0; sA[s][0][m][c0 + 2] = h1;
            sA[s][1][m][c0] = l0; sA[s][1][m][c0 + 2] = l1;
        }
    };
    auto domma = [&](int s) {
        unsigned ah[2][4], al[2][4];
#pragma unroll
        for (int t = 0; t < 2; t++) {
            int r0 = wm + t * 16 + g;
            uint2 u0 = *(const uint2*)&sA[s][0][r0][2 * tg];
            uint2 u1 = *(const uint2*)&sA[s][0][r0 + 8][2 * tg];
            ah[t][0] = u0.x; ah[t][1] = u1.x; ah[t][2] = u0.y; ah[t][3] = u1.y;
            uint2 w0 = *(const uint2*)&sA[s][1][r0][2 * tg];
            uint2 w1 = *(const uint2*)&sA[s][1][r0 + 8][2 * tg];
            al[t][0] = w0.x; al[t][1] = w1.x; al[t][2] = w0.y; al[t][3] = w1.y;
        }
#pragma unroll
        for (int nt = 0; nt < 8; nt++) {
            int n0 = wn + nt * 8 + g;
            uint2 bh = *(const uint2*)&sB[s][n0][2 * tg];
#pragma unroll
            for (int t = 0; t < 2; t++) {
                mma_f16(d[t][nt], ah[t], bh.x, bh.y); // hi*B
                mma_f16(d[t][nt], al[t], bh.x, bh.y); // lo*B
            }
        }
    };

    // ---- prologue: fill stage 0 ----
    {
        stageB(0, 0);
        CP_COMMIT();
        float4 v0[2];
        ldgA(0, v0);
        stsA(0, 0, v0);
        CP_WAIT0();
    }
    __syncthreads();

    // ---- pipelined mainloop ----
    float4 vr[2];
    for (int c = 0; c < NCH; ++c) {
        int cs = c & 1, ns = cs ^ 1;
        bool more = (c + 1 < NCH);
        if (more) {
            stageB(ns, c + 1);
            CP_COMMIT();
            ldgA(c + 1, vr);
        }
        domma(cs);
        if (more) {
            stsA(ns, c + 1, vr);
            CP_WAIT0();
        }
        __syncthreads();
    }

    // ---------------- epilogue ----------------
    float* wbs = (float*)sA;               // 512 floats, aliased
    float* Tred = (float*)&sA[0][1][0][0]; // 512 floats, aliased
    if (TMIX) {
        for (int i = tid; i < 512; i += 256) wbs[i] = WB[i];
        if (tid < 128) {
            Tred[tid * 4 + 0] = 0.f; Tred[tid * 4 + 1] = 0.f;
            Tred[tid * 4 + 2] = 0.f; Tred[tid * 4 + 3] = 0.f;
        }
        __syncthreads();
    }

    float tp[4][4];
    if (TMIX) {
#pragma unroll
        for (int s = 0; s < 4; s++)
#pragma unroll
            for (int m = 0; m < 4; m++) tp[s][m] = 0.f;
    }
#pragma unroll
    for (int t = 0; t < 2; t++) {
        int r = m0 + wm + t * 16 + g;
#pragma unroll
        for (int nt = 0; nt < 8; nt++) {
            int c = wn + nt * 8 + 2 * tg;
            float b0 = 0.f, b1 = 0.f;
            if (BIAS) { b0 = bias[c]; b1 = bias[c + 1]; }
            float v0 = d[t][nt][0] + b0, v1 = d[t][nt][1] + b1;
            float v2 = d[t][nt][2] + b0, v3 = d[t][nt][3] + b1;
            if (GOUT) {
                v0 = gelu_f(v0); v1 = gelu_f(v1);
                v2 = gelu_f(v2); v3 = gelu_f(v3);
            }
            if (TMIX) {
#pragma unroll
                for (int m = 0; m < 4; m++) {
                    float w0 = wbs[m * 128 + c], w1 = wbs[m * 128 + c + 1];
                    tp[t * 2 + 0][m] += v0 * w0 + v1 * w1;
                    tp[t * 2 + 1][m] += v2 * w0 + v3 * w1;
                }
            } else {
                if (r < rows)
                    *(float2*)(C + (long)r * 128 + c) = make_float2(v0, v1);
                if (r + 8 < rows)
                    *(float2*)(C + (long)(r + 8) * 128 + c) = make_float2(v2, v3);
            }
        }
    }

    if (TMIX) {
#pragma unroll
        for (int off = 1; off < 4; off <<= 1)
#pragma unroll
            for (int s = 0; s < 4; s++)
#pragma unroll
                for (int m = 0; m < 4; m++)
                    tp[s][m] += __shfl_xor_sync(0xffffffffu, tp[s][m], off);
        if (tg == 0) {
#pragma unroll
            for (int s = 0; s < 4; s++) {
                int rl = wm + g + ((s & 1) ? 8 : 0) + ((s >> 1) ? 16 : 0);
#pragma unroll
                for (int m = 0; m < 4; m++) atomicAdd(&Tred[rl * 4 + m], tp[s][m]);
            }
        }
        __syncthreads();
        if (tid < 128) {
            int r = m0 + tid;
            if (r < rows)
                *(float4*)(g_T + (long)r * 4) =
                    make_float4(Tred[tid * 4 + 0], Tred[tid * 4 + 1],
                                Tred[tid * 4 + 2], Tred[tid * 4 + 3]);
        }
    }
}

// ---------------- edge counting sort by dst ----------------
__global__ void k_hist(const void* __restrict__ EI) {
    for (int e = blockIdx.x * blockDim.x + threadIdx.x; e < NE;
         e += gridDim.x * blockDim.x) {
        int d = edge_at(EI, 1, e);
        if (d >= 0 && d < NN) atomicAdd(&g_deg[d], 1);
    }
}

__global__ void k_scan() {
    __shared__ int smv[1024];
    int t = threadIdx.x;
    const int CH = 49; // 1024*49 >= 50000
    int base = t * CH;
    int s = 0;
    for (int i = 0; i < CH; i++) {
        int idx = base + i;
        if (idx < NN) s += g_deg[idx];
    }
    smv[t] = s;
    __syncthreads();
    for (int off = 1; off < 1024; off <<= 1) {
        int v = (t >= off) ? smv[t - off] : 0;
        __syncthreads();
        smv[t] += v;
        __syncthreads();
    }
    int run = smv[t] - s;
    for (int i = 0; i < CH; i++) {
        int idx = base + i;
        if (idx < NN) {
            g_off[idx] = run;
            g_cur[idx] = run;
            run += g_deg[idx];
        }
    }
    if (t == 0) g_off[NN] = NE;
}

__global__ void k_scatter(const void* __restrict__ EI) {
    for (int e = blockIdx.x * blockDim.x + threadIdx.x; e < NE;
         e += gridDim.x * blockDim.x) {
        int d = edge_at(EI, 1, e);
        int s = edge_at(EI, 0, e);
        if (d >= 0 && d < NN) {
            int p = atomicAdd(&g_cur[d], 1);
            g_srcs[p] = s;
        }
    }
}

// ---------------- per-node aggregation (warp per node, 4-edge unroll) -----
// lane handles 4 contiguous H columns (single LDG.128 gather per edge).
// aggnode[n][h] = gelu( (sum_m gelu(acc[h][m]) * S[m]) / max(deg,1) )
__global__ void k_agg() {
    int warp = threadIdx.x >> 5, lane = threadIdx.x & 31;
    int n = blockIdx.x * 8 + warp;
    if (n >= NN) return;
    int beg = g_off[n], end = g_off[n + 1];
    float acc[4][4]; // [col-within-float4][mix]
#pragma unroll
    for (int sg = 0; sg < 4; sg++)
#pragma unroll
        for (int m = 0; m < 4; m++) acc[sg][m] = 0.f;
    float S[4] = {0, 0, 0, 0};
    int i = beg;
    for (; i + 3 < end; i += 4) {
        int s[4];
        float4 t4[4];
        float4 h4[4];
#pragma unroll
        for (int e = 0; e < 4; e++) s[e] = g_srcs[i + e];
#pragma unroll
        for (int e = 0; e < 4; e++) {
            t4[e] = *(const float4*)(g_T + (long)s[e] * 4);
            h4[e] = *(const float4*)(g_H + (long)s[e] * 128 + 4 * lane);
        }
#pragma unroll
        for (int e = 0; e < 4; e++) {
            float tm[4] = {t4[e].x, t4[e].y, t4[e].z, t4[e].w};
            float hv[4] = {h4[e].x, h4[e].y, h4[e].z, h4[e].w};
#pragma unroll
            for (int m = 0; m < 4; m++) {
                S[m] += tm[m];
#pragma unroll
                for (int sg = 0; sg < 4; sg++) acc[sg][m] += hv[sg] * tm[m];
            }
        }
    }
    for (; i < end; ++i) {
        int s0 = g_srcs[i];
        float4 t4 = *(const float4*)(g_T + (long)s0 * 4);
        float4 h4 = *(const float4*)(g_H + (long)s0 * 128 + 4 * lane);
        float tm[4] = {t4.x, t4.y, t4.z, t4.w};
        float hv[4] = {h4.x, h4.y, h4.z, h4.w};
#pragma unroll
        for (int m = 0; m < 4; m++) {
            S[m] += tm[m];
#pragma unroll
            for (int sg = 0; sg < 4; sg++) acc[sg][m] += hv[sg] * tm[m];
        }
    }
    int cnt = end - beg;
    float inv = 1.0f / (float)(cnt > 1 ? cnt : 1);
    float4 o;
    o.x = gelu_f((gelu_f(acc[0][0]) * S[0] + gelu_f(acc[0][1]) * S[1] +
                  gelu_f(acc[0][2]) * S[2] + gelu_f(acc[0][3]) * S[3]) * inv);
    o.y = gelu_f((gelu_f(acc[1][0]) * S[0] + gelu_f(acc[1][1]) * S[1] +
                  gelu_f(acc[1][2]) * S[2] + gelu_f(acc[1][3]) * S[3]) * inv);
    o.z = gelu_f((gelu_f(acc[2][0]) * S[0] + gelu_f(acc[2][1]) * S[1] +
                  gelu_f(acc[2][2]) * S[2] + gelu_f(acc[2][3]) * S[3]) * inv);
    o.w = gelu_f((gelu_f(acc[3][0]) * S[0] + gelu_f(acc[3][1]) * S[1] +
                  gelu_f(acc[3][2]) * S[2] + gelu_f(acc[3][3]) * S[3]) * inv);
    *(float4*)(g_aggnode + (long)n * 128 + 4 * lane) = o;
}

// ---------------- host launch: kernel launches ONLY ----------------
extern "C" void kernel_launch(void* const* d_in, const int* in_sizes, int n_in,
                              void* d_out, int out_size) {
    const float* X = (const float*)d_in[0];
    const void* EI = d_in[1];
    const float* W1 = (const float*)d_in[2];
    const float* b1 = (const float*)d_in[3];
    const float* WA = (const float*)d_in[4];
    const float* WB = (const float*)d_in[5];
    const float* W2 = (const float*)d_in[6];
    const float* b2 = (const float*)d_in[7];
    float* out = (float*)d_out;

    k_zerodeg<<<(NN + 255) / 256, 256>>>();
    k_detect<<<256, 256>>>((const unsigned int*)EI);
    k_wsplit<<<128, 256>>>(W1, WA, W2);

    int gg = (NN + 127) / 128; // 391
    // H = gelu(X W1^T + b1)
    k_gemm_hf<128, true, true, false, false><<<gg, 256>>>(
        X, -1, -1, b1, 0, nullptr, nullptr, 1, NN);
    // T = gelu(H WA^T) WB^T   (G never materialized)
    k_gemm_hf<128, true, false, false, true><<<gg, 256>>>(
        nullptr, 1, -1, nullptr, 1, WB, nullptr, -1, NN);

    // edge counting sort by dst
    k_hist<<<512, 256>>>(EI);
    k_scan<<<1, 1024>>>();
    k_scatter<<<512, 256>>>(EI);

    // fused aggregation (+ concat-gelu on the agg half)
    k_agg<<<(NN + 7) / 8, 256>>>();

    // out = [gelu(agg) | gelu(H)] W2^T + b2   (virtual concat)
    k_gemm_hf<256, false, true, true, false><<<gg, 256>>>(
        nullptr, 5, 1, b2, 2, nullptr, out, -1, NN);
}

// round 15
// speedup vs baseline: 1.6344x; 1.4339x over previous
#include <cuda_runtime.h>
#include <cuda_fp16.h>
#include <cstdint>

#define NN 50000
#define NE 400000
#define DD 128
#define MM 4
#define GG 391          // GEMM M-tiles
#define NDPAD 50176     // 256*196, padded for vectorized scan

// ---------------- device scratch ----------------
__device__ __align__(16) float g_H[NN * DD];       // 1: H = gelu(X W1^T + b1)
__device__ __align__(16) float g_aggnode[NN * DD]; // 5: gelu(aggregated features)
__device__ __align__(16) float g_T[NN * MM];       // per-node hyper weights
// pre-packed fp16 weight pairs, fragment-physical pair order
__device__ __align__(16) unsigned g_W1h[DD * DD / 2];
__device__ __align__(16) unsigned g_WAh[DD * DD / 2];
__device__ __align__(16) unsigned g_W2h[DD * DD];
__device__ __align__(16) int g_deg[NDPAD];
__device__ __align__(16) int g_off[NDPAD + 16];
__device__ __align__(16) int g_cur[NDPAD + 16];
__device__ int g_srcs[NE];
__device__ int g_is32 = 0; // set-only: 1 if edge_index is int32

__device__ __forceinline__ float* get_buf(int id) {
    switch (id) {
        case 1: return g_H;
        case 5: return g_aggnode;
    }
    return g_H;
}
__device__ __forceinline__ const unsigned* get_wh(int id) {
    switch (id) {
        case 0: return g_W1h;
        case 1: return g_WAh;
        case 2: return g_W2h;
    }
    return g_W1h;
}

// ---------------- helpers ----------------
__device__ __forceinline__ float gelu_f(float x) {
    return 0.5f * x * (1.0f + erff(x * 0.7071067811865476f));
}

__device__ __forceinline__ unsigned pack2h(float x, float y) {
    __half2 p = __floats2half2_rn(x, y);
    return *reinterpret_cast<unsigned*>(&p);
}

// split (x,y) into fp16 hi pair + fp16 residual-lo pair (A exact to 2^-24)
__device__ __forceinline__ void split2h(float x, float y, unsigned& hi, unsigned& lo) {
    __half hx = __float2half_rn(x);
    __half hy = __float2half_rn(y);
    __half2 ph;
    ph.x = hx;
    ph.y = hy;
    hi = *reinterpret_cast<unsigned*>(&ph);
    lo = pack2h(x - __half2float(hx), y - __half2float(hy));
}

__device__ __forceinline__ void mma_f16(float* d, const unsigned* a,
                                        unsigned b0, unsigned b1) {
    asm volatile(
        "mma.sync.aligned.m16n8k16.row.col.f32.f16.f16.f32 "
        "{%0,%1,%2,%3}, {%4,%5,%6,%7}, {%8,%9}, {%0,%1,%2,%3};\n"
        : "+f"(d[0]), "+f"(d[1]), "+f"(d[2]), "+f"(d[3])
        : "r"(a[0]), "r"(a[1]), "r"(a[2]), "r"(a[3]), "r"(b0), "r"(b1));
}

// physical column for logical k-pair p within an 8-pair (k16) group
__device__ __forceinline__ int physcol8(int p) {
    return ((p & 3) << 1) | (p >> 2);
}

__device__ __forceinline__ uint32_t smem_u32(const void* p) {
    uint32_t a;
    asm("{ .reg .u64 t; cvta.to.shared.u64 t, %1; cvt.u32.u64 %0, t; }"
        : "=r"(a) : "l"(p));
    return a;
}

#define CP_ASYNC16(dst, src) \
    asm volatile("cp.async.cg.shared.global [%0], [%1], 16;" \
                 :: "r"(dst), "l"(src) : "memory")
#define CP_COMMIT() asm volatile("cp.async.commit_group;" ::: "memory")
#define CP_WAIT0() asm volatile("cp.async.wait_group 0;" ::: "memory")

// edge accessor robust to int32 vs int64 storage. which: 0 = src, 1 = dst.
__device__ __forceinline__ int edge_at(const void* EI, int which, int e) {
    if (g_is32) return ((const int*)EI)[which * NE + e];
    return (int)((const long long*)EI)[which * NE + e];
}

// ---------------- fused init: zero deg + dtype detect + weight pack -------
__global__ void k_init(const unsigned int* __restrict__ w,
                       const float* __restrict__ W1, const float* __restrict__ WA,
                       const float* __restrict__ W2) {
    int gt = blockIdx.x * blockDim.x + threadIdx.x;
    int gs = gridDim.x * blockDim.x;
    for (int i = gt; i < NDPAD; i += gs) g_deg[i] = 0;
    unsigned v = 0;
    for (int j = gt; j < NE; j += gs) v |= w[2 * j + 1];
    if (v) g_is32 = 1; // set-only; deterministic for fixed inputs
    for (int i = gt; i < 32768; i += gs) {
        const float* src;
        unsigned* dh;
        int p, K2len;
        if (i < 8192) {
            src = W1; dh = g_W1h; p = i; K2len = 64;
        } else if (i < 16384) {
            src = WA; dh = g_WAh; p = i - 8192; K2len = 64;
        } else {
            src = W2; dh = g_W2h; p = i - 16384; K2len = 128;
        }
        float2 fv = *(const float2*)(src + 2 * p);
        int n = p / K2len, col = p % K2len;
        int pc = (col & ~7) | physcol8(col & 7);
        dh[n * K2len + pc] = pack2h(fv.x, fv.y);
    }
}

// ---------------- fp16 2-term GEMM body (device fn, tile = bx) ------------
template <int K, bool GOUT, bool BIAS, bool SPLITA, bool TMIX>
__device__ __forceinline__ void gemm_dev(
    int bx, const float* __restrict__ Aext, int aId, int a2Id,
    const float* __restrict__ bias, int wId, const float* __restrict__ WB,
    float* __restrict__ Cext, int cId, int rows) {
    __shared__ __align__(16) unsigned sA[2][2][128][12]; // [stage][hi/lo][m][pc]
    __shared__ __align__(16) unsigned sB[2][128][12];    // [stage][n][pc]

    const float* A1 = Aext ? Aext : get_buf(aId);
    const float* A2 = SPLITA ? get_buf(a2Id) : nullptr;
    const unsigned* Wh = get_wh(wId);
    float* C = Cext ? Cext : get_buf(cId);
    const int K2 = K / 2;
    const int NCH = K / 16;

    int tid = threadIdx.x;
    int wid = tid >> 5, lane = tid & 31;
    int wm = (wid >> 1) * 32;  // warp M base
    int wn = (wid & 1) * 64;   // warp N base
    int g = lane >> 2, tg = lane & 3;
    int m0 = bx * 128;

    float d[2][8][4];
#pragma unroll
    for (int t = 0; t < 2; t++)
#pragma unroll
        for (int nt = 0; nt < 8; nt++)
#pragma unroll
            for (int j = 0; j < 4; j++) d[t][nt][j] = 0.f;

    int brow = tid >> 1, bq = tid & 1;
    auto stageB = [&](int s, int c) {
        uint32_t d0 = smem_u32(&sB[s][brow][bq * 4]);
        CP_ASYNC16(d0, Wh + (long)brow * K2 + 8 * c + 4 * bq);
    };
    auto ldgA = [&](int c, float4* vr) {
        const float* Ap = A1;
        int kk = c * 16;
        if (SPLITA && kk >= 128) { Ap = A2; kk -= 128; }
#pragma unroll
        for (int i = 0; i < 2; ++i) {
            int f = tid + (i << 8);
            int m = f >> 2, kq = (f & 3) << 2;
            int gm = m0 + m;
            vr[i] = (gm < rows) ? *(const float4*)(Ap + (long)gm * 128 + kk + kq)
                                : make_float4(0.f, 0.f, 0.f, 0.f);
        }
    };
    auto stsA = [&](int s, int c, float4* vr) {
        bool ag = SPLITA && (c * 16 >= 128);
#pragma unroll
        for (int i = 0; i < 2; ++i) {
            int f = tid + (i << 8);
            int m = f >> 2, kq = (f & 3) << 2;
            int p = kq >> 1; // even
            int c0 = physcol8(p);
            float4 v = vr[i];
            if (ag) {
                v.x = gelu_f(v.x); v.y = gelu_f(v.y);
                v.z = gelu_f(v.z); v.w = gelu_f(v.w);
            }
            unsigned h0, l0, h1, l1;
            split2h(v.x, v.y, h0, l0);
            split2h(v.z, v.w, h1, l1);
            sA[s][0][m][c0] = h0; sA[s][0][m][c0 + 2] = h1;
            sA[s][1][m][c0] = l0; sA[s][1][m][c0 + 2] = l1;
        }
    };
    auto domma = [&](int s) {
        unsigned ah[2][4], al[2][4];
#pragma unroll
        for (int t = 0; t < 2; t++) {
            int r0 = wm + t * 16 + g;
            uint2 u0 = *(const uint2*)&sA[s][0][r0][2 * tg];
            uint2 u1 = *(const uint2*)&sA[s][0][r0 + 8][2 * tg];
            ah[t][0] = u0.x; ah[t][1] = u1.x; ah[t][2] = u0.y; ah[t][3] = u1.y;
            uint2 w0 = *(const uint2*)&sA[s][1][r0][2 * tg];
            uint2 w1 = *(const uint2*)&sA[s][1][r0 + 8][2 * tg];
            al[t][0] = w0.x; al[t][1] = w1.x; al[t][2] = w0.y; al[t][3] = w1.y;
        }
#pragma unroll
        for (int nt = 0; nt < 8; nt++) {
            int n0 = wn + nt * 8 + g;
            uint2 bh = *(const uint2*)&sB[s][n0][2 * tg];
#pragma unroll
            for (int t = 0; t < 2; t++) {
                mma_f16(d[t][nt], ah[t], bh.x, bh.y); // hi*B
                mma_f16(d[t][nt], al[t], bh.x, bh.y); // lo*B
            }
        }
    };

    // ---- prologue ----
    {
        stageB(0, 0);
        CP_COMMIT();
        float4 v0[2];
        ldgA(0, v0);
        stsA(0, 0, v0);
        CP_WAIT0();
    }
    __syncthreads();

    // ---- pipelined mainloop ----
    float4 vr[2];
    for (int c = 0; c < NCH; ++c) {
        int cs = c & 1, ns = cs ^ 1;
        bool more = (c + 1 < NCH);
        if (more) {
            stageB(ns, c + 1);
            CP_COMMIT();
            ldgA(c + 1, vr);
        }
        domma(cs);
        if (more) {
            stsA(ns, c + 1, vr);
            CP_WAIT0();
        }
        __syncthreads();
    }

    // ---------------- epilogue ----------------
    float* wbs = (float*)sA;               // 512 floats, aliased
    float* Tred = (float*)&sA[0][1][0][0]; // 512 floats, aliased
    if (TMIX) {
        for (int i = tid; i < 512; i += 256) wbs[i] = WB[i];
        if (tid < 128) {
            Tred[tid * 4 + 0] = 0.f; Tred[tid * 4 + 1] = 0.f;
            Tred[tid * 4 + 2] = 0.f; Tred[tid * 4 + 3] = 0.f;
        }
        __syncthreads();
    }

    float tp[4][4];
    if (TMIX) {
#pragma unroll
        for (int s = 0; s < 4; s++)
#pragma unroll
            for (int m = 0; m < 4; m++) tp[s][m] = 0.f;
    }
#pragma unroll
    for (int t = 0; t < 2; t++) {
        int r = m0 + wm + t * 16 + g;
#pragma unroll
        for (int nt = 0; nt < 8; nt++) {
            int c = wn + nt * 8 + 2 * tg;
            float b0 = 0.f, b1 = 0.f;
            if (BIAS) { b0 = bias[c]; b1 = bias[c + 1]; }
            float v0 = d[t][nt][0] + b0, v1 = d[t][nt][1] + b1;
            float v2 = d[t][nt][2] + b0, v3 = d[t][nt][3] + b1;
            if (GOUT) {
                v0 = gelu_f(v0); v1 = gelu_f(v1);
                v2 = gelu_f(v2); v3 = gelu_f(v3);
            }
            if (TMIX) {
#pragma unroll
                for (int m = 0; m < 4; m++) {
                    float w0 = wbs[m * 128 + c], w1 = wbs[m * 128 + c + 1];
                    tp[t * 2 + 0][m] += v0 * w0 + v1 * w1;
                    tp[t * 2 + 1][m] += v2 * w0 + v3 * w1;
                }
            } else {
                if (r < rows)
                    *(float2*)(C + (long)r * 128 + c) = make_float2(v0, v1);
                if (r + 8 < rows)
                    *(float2*)(C + (long)(r + 8) * 128 + c) = make_float2(v2, v3);
            }
        }
    }

    if (TMIX) {
#pragma unroll
        for (int off = 1; off < 4; off <<= 1)
#pragma unroll
            for (int s = 0; s < 4; s++)
#pragma unroll
                for (int m = 0; m < 4; m++)
                    tp[s][m] += __shfl_xor_sync(0xffffffffu, tp[s][m], off);
        if (tg == 0) {
#pragma unroll
            for (int s = 0; s < 4; s++) {
                int rl = wm + g + ((s & 1) ? 8 : 0) + ((s >> 1) ? 16 : 0);
#pragma unroll
                for (int m = 0; m < 4; m++) atomicAdd(&Tred[rl * 4 + m], tp[s][m]);
            }
        }
        __syncthreads();
        if (tid < 128) {
            int r = m0 + tid;
            if (r < rows)
                *(float4*)(g_T + (long)r * 4) =
                    make_float4(Tred[tid * 4 + 0], Tred[tid * 4 + 1],
                                Tred[tid * 4 + 2], Tred[tid * 4 + 3]);
        }
    }
}

// ---------------- hist device fn (grid-slice [0, nctas)) ------------------
__device__ __forceinline__ void hist_dev(const void* EI, int cta, int nctas) {
    for (int e = cta * 256 + threadIdx.x; e < NE; e += nctas * 256) {
        int dd = edge_at(EI, 1, e);
        if (dd >= 0 && dd < NN) atomicAdd(&g_deg[dd], 1);
    }
}

// ---------------- scan device fn (one CTA, 256 threads, vectorized) -------
__device__ __forceinline__ void scan_dev() {
    __shared__ int smv[256];
    int t = threadIdx.x;
    const int CH = 196; // 256*196 = 50176 = NDPAD (padding zeroed in k_init)
    int base = t * CH;
    int s = 0;
#pragma unroll 7
    for (int i = 0; i < 49; i++) {
        int4 v = *(const int4*)(g_deg + base + i * 4);
        s += v.x + v.y + v.z + v.w;
    }
    smv[t] = s;
    __syncthreads();
    for (int off = 1; off < 256; off <<= 1) {
        int v = (t >= off) ? smv[t - off] : 0;
        __syncthreads();
        smv[t] += v;
        __syncthreads();
    }
    int run = smv[t] - s; // exclusive prefix
#pragma unroll 7
    for (int i = 0; i < 49; i++) {
        int4 v = *(const int4*)(g_deg + base + i * 4);
        int4 o;
        o.x = run;
        o.y = run + v.x;
        o.z = o.y + v.y;
        o.w = o.z + v.z;
        *(int4*)(g_off + base + i * 4) = o;
        *(int4*)(g_cur + base + i * 4) = o;
        run = o.w + v.w;
    }
}

// ---------------- fused launches ----------------
// GEMM1 tiles || histogram
__global__ void __launch_bounds__(256, 2)
k_pipe1(const float* __restrict__ X, const float* __restrict__ b1,
        const void* __restrict__ EI) {
    int bx = blockIdx.x;
    if (bx < GG)
        gemm_dev<128, true, true, false, false>(bx, X, -1, -1, b1, 0, nullptr,
                                                nullptr, 1, NN);
    else
        hist_dev(EI, bx - GG, 512);
}

// GEMM2 (TMIX -> T) || prefix scan
__global__ void __launch_bounds__(256, 2)
k_pipe2(const float* __restrict__ WB) {
    int bx = blockIdx.x;
    if (bx < GG)
        gemm_dev<128, true, false, false, true>(bx, nullptr, 1, -1, nullptr, 1,
                                                WB, nullptr, -1, NN);
    else
        scan_dev();
}

// GEMM3: out = [gelu(agg) | gelu(H)] W2^T + b2
__global__ void __launch_bounds__(256, 2)
k_gemm3(const float* __restrict__ b2, float* __restrict__ out) {
    gemm_dev<256, false, true, true, false>(blockIdx.x, nullptr, 5, 1, b2, 2,
                                            nullptr, out, -1, NN);
}

// ---------------- scatter (counting-sort placement) ----------------
__global__ void k_scatter(const void* __restrict__ EI) {
    for (int e = blockIdx.x * blockDim.x + threadIdx.x; e < NE;
         e += gridDim.x * blockDim.x) {
        int d = edge_at(EI, 1, e);
        int s = edge_at(EI, 0, e);
        if (d >= 0 && d < NN) {
            int p = atomicAdd(&g_cur[d], 1);
            g_srcs[p] = s;
        }
    }
}

// ---------------- per-node aggregation (warp per node, 4-edge unroll) -----
// lane handles 4 contiguous H columns (single LDG.128 gather per edge).
// aggnode[n][h] = gelu( (sum_m gelu(acc[h][m]) * S[m]) / max(deg,1) )
__global__ void k_agg() {
    int warp = threadIdx.x >> 5, lane = threadIdx.x & 31;
    int n = blockIdx.x * 8 + warp;
    if (n >= NN) return;
    int beg = g_off[n], end = g_off[n + 1];
    float acc[4][4]; // [col-within-float4][mix]
#pragma unroll
    for (int sg = 0; sg < 4; sg++)
#pragma unroll
        for (int m = 0; m < 4; m++) acc[sg][m] = 0.f;
    float S[4] = {0, 0, 0, 0};
    int i = beg;
    for (; i + 3 < end; i += 4) {
        int s[4];
        float4 t4[4];
        float4 h4[4];
#pragma unroll
        for (int e = 0; e < 4; e++) s[e] = g_srcs[i + e];
#pragma unroll
        for (int e = 0; e < 4; e++) {
            t4[e] = *(const float4*)(g_T + (long)s[e] * 4);
            h4[e] = *(const float4*)(g_H + (long)s[e] * 128 + 4 * lane);
        }
#pragma unroll
        for (int e = 0; e < 4; e++) {
            float tm[4] = {t4[e].x, t4[e].y, t4[e].z, t4[e].w};
            float hv[4] = {h4[e].x, h4[e].y, h4[e].z, h4[e].w};
#pragma unroll
            for (int m = 0; m < 4; m++) {
                S[m] += tm[m];
#pragma unroll
                for (int sg = 0; sg < 4; sg++) acc[sg][m] += hv[sg] * tm[m];
            }
        }
    }
    for (; i < end; ++i) {
        int s0 = g_srcs[i];
        float4 t4 = *(const float4*)(g_T + (long)s0 * 4);
        float4 h4 = *(const float4*)(g_H + (long)s0 * 128 + 4 * lane);
        float tm[4] = {t4.x, t4.y, t4.z, t4.w};
        float hv[4] = {h4.x, h4.y, h4.z, h4.w};
#pragma unroll
        for (int m = 0; m < 4; m++) {
            S[m] += tm[m];
#pragma unroll
            for (int sg = 0; sg < 4; sg++) acc[sg][m] += hv[sg] * tm[m];
        }
    }
    int cnt = end - beg;
    float inv = 1.0f / (float)(cnt > 1 ? cnt : 1);
    float4 o;
    o.x = gelu_f((gelu_f(acc[0][0]) * S[0] + gelu_f(acc[0][1]) * S[1] +
                  gelu_f(acc[0][2]) * S[2] + gelu_f(acc[0][3]) * S[3]) * inv);
    o.y = gelu_f((gelu_f(acc[1][0]) * S[0] + gelu_f(acc[1][1]) * S[1] +
                  gelu_f(acc[1][2]) * S[2] + gelu_f(acc[1][3]) * S[3]) * inv);
    o.z = gelu_f((gelu_f(acc[2][0]) * S[0] + gelu_f(acc[2][1]) * S[1] +
                  gelu_f(acc[2][2]) * S[2] + gelu_f(acc[2][3]) * S[3]) * inv);
    o.w = gelu_f((gelu_f(acc[3][0]) * S[0] + gelu_f(acc[3][1]) * S[1] +
                  gelu_f(acc[3][2]) * S[2] + gelu_f(acc[3][3]) * S[3]) * inv);
    *(float4*)(g_aggnode + (long)n * 128 + 4 * lane) = o;
}

// ---------------- host launch: kernel launches ONLY ----------------
extern "C" void kernel_launch(void* const* d_in, const int* in_sizes, int n_in,
                              void* d_out, int out_size) {
    const float* X = (const float*)d_in[0];
    const void* EI = d_in[1];
    const float* W1 = (const float*)d_in[2];
    const float* b1 = (const float*)d_in[3];
    const float* WA = (const float*)d_in[4];
    const float* WB = (const float*)d_in[5];
    const float* W2 = (const float*)d_in[6];
    const float* b2 = (const float*)d_in[7];
    float* out = (float*)d_out;

    // init: zero deg (padded), detect edge dtype, pack weights to fp16
    k_init<<<256, 256>>>((const unsigned int*)EI, W1, WA, W2);

    // GEMM1 (H = gelu(X W1^T + b1)) overlapped with edge histogram
    k_pipe1<<<GG + 512, 256>>>(X, b1, EI);

    // GEMM2 (T = gelu(H WA^T) WB^T) overlapped with prefix scan
    k_pipe2<<<GG + 1, 256>>>(WB);

    // counting-sort placement
    k_scatter<<<512, 256>>>(EI);

    // fused aggregation (+ concat-gelu on the agg half)
    k_agg<<<(NN + 7) / 8, 256>>>();

    // out = [gelu(agg) | gelu(H)] W2^T + b2   (virtual concat)
    k_gemm3<<<GG, 256>>>(b2, out);
}